// round 8
// baseline (speedup 1.0000x reference)
#include <cuda_runtime.h>

//
// Morphological skeleton — merged erode+dilate, one smem pass per iteration.
// R7: 128x64 tiles, 2 CTAs/SM to overlap barrier stalls across CTAs.
//
//   skel = sum_{j=0..K-1} x_j  -  sum_{j=1..K} dilate3(x_j),  x_{j+1} = erode3(x_j)
//

#define IMG    1024
#define NIMG   16
#define TW     128                 /* tile width                  */
#define TH     64                  /* tile height                 */
#define HALO   12
#define RWW    152                 /* region width  (TW+2*HALO)   */
#define RWH    88                  /* region height (TH+2*HALO)   */
#define RWP    156                 /* padded row stride: 156%32=28 (no cross-strip bank aliasing) */
#define NCOL   38                  /* float4 columns: cover 152   */
#define NSTR   8
#define RPS    11                  /* 8*11 = 88 rows exactly      */
#define ACT    (NCOL*NSTR)         /* 304 active threads          */
#define NT     320                 /* 10 warps                    */
#define SMEMB  (2 * RWH * RWP * 4) /* 109824 bytes                */

__device__ float g_scratch[(size_t)NIMG * IMG * IMG];

__device__ __forceinline__ float min3f(float a, float b, float c) { return fminf(fminf(a, b), c); }
__device__ __forceinline__ float max3f(float a, float b, float c) { return fmaxf(fmaxf(a, b), c); }

// One row-block: 1x LDS.128 + 2x independent scalar LDS (no shuffles — the
// scalar loads overlap with the vector load; shfl serializes, measured 2x).
__device__ __forceinline__ void rowmm(const float* __restrict__ row, int xb,
                                      float4& v, float4& mn, float4& mx,
                                      bool doMn, bool doMx)
{
    v = *(const float4*)(row + xb);
    float l = (xb > 0)        ? row[xb - 1] : v.x;  // region-edge replicate (min-safe;
    float r = (xb + 4 < RWW)  ? row[xb + 4] : v.w;  //  never feeds interior dilate)
    if (doMn) {
        mn.x = min3f(l,   v.x, v.y);
        mn.y = min3f(v.x, v.y, v.z);
        mn.z = min3f(v.y, v.z, v.w);
        mn.w = min3f(v.z, v.w, r);
    }
    if (doMx) {
        mx.x = max3f(l,   v.x, v.y);
        mx.y = max3f(v.x, v.y, v.z);
        mx.z = max3f(v.y, v.z, v.w);
        mx.w = max3f(v.z, v.w, r);
    }
}

__global__ void __launch_bounds__(NT, 2)
skel_merged_kernel(const float* __restrict__ xin,
                   float* __restrict__ xout,
                   float* __restrict__ skel,
                   int K, int accum, int writex)
{
    extern __shared__ float smem[];
    float* cur = smem;              // x_p
    float* nxt = smem + RWH * RWP;  // receives x_{p+1}

    const int tid = threadIdx.x;
    const int bx = blockIdx.x, by = blockIdx.y, bz = blockIdx.z;
    const int gx0 = bx * TW - HALO;
    const int gy0 = by * TH - HALO;
    const float* img = xin + (size_t)bz * IMG * IMG;

    // ---- load region with replicate clamp ----
    for (int i = tid; i < RWH * RWW; i += NT) {
        int y = i / RWW;
        int x = i - y * RWW;
        int gy = min(max(gy0 + y, 0), IMG - 1);
        int gx = min(max(gx0 + x, 0), IMG - 1);
        cur[y * RWP + x] = img[(size_t)gy * IMG + gx];
    }
    __syncthreads();

    const bool topE   = (by == 0);
    const bool botE   = (by == (int)gridDim.y - 1);
    const bool leftE  = (bx == 0);
    const bool rightE = (bx == (int)gridDim.x - 1);
    const bool anyE   = topE || botE || leftE || rightE;

    const bool active = (tid < ACT);
    const int c  = active ? (tid % NCOL) : 0;     // float4 column 0..37
    const int s  = active ? (tid / NCOL) : 0;     // strip 0..7
    const int xb = c * 4;                         // 0..148
    const bool dcol = active && (xb >= HALO) && (xb + 4 <= HALO + TW);
    const int y0 = s * RPS;

    float4 acc[RPS];
#pragma unroll
    for (int k = 0; k < RPS; k++) acc[k] = make_float4(0.f, 0.f, 0.f, 0.f);

    for (int p = 0; p <= K; ++p) {
        const bool doE = (p < K);
        const bool doD = (p > 0);
        const bool doMx = doD && dcol;            // hmax consumed only here
        const int  m   = K - p;                   // erode validity margin (rows)
        const int  elo = doE ? (HALO - m) : HALO;
        const int  ehi = doE ? (HALO + TH + m) : (HALO + TH);

        if (active && (doE || dcol)) {
            // prime 3-row ring (vertical replicate clamp; min-safe, clamped
            // rows never reach interior dilate consumers)
            float4 av, amn, amx, bv, bmn, bmx;
            rowmm(cur + max(y0 - 1, 0) * RWP, xb, av, amn, amx, doE, doMx);
            rowmm(cur + y0 * RWP,             xb, bv, bmn, bmx, doE, doMx);

#pragma unroll
            for (int k = 0; k < RPS; k++) {
                const int y = y0 + k;
                float4 cv, cmn, cmx;
                rowmm(cur + min(y + 1, RWH - 1) * RWP, xb, cv, cmn, cmx, doE, doMx);

                // skel terms at interior rows: += x_p (p<K), -= dilate(x_p) (p>0)
                if (dcol && y >= HALO && y < HALO + TH) {
                    if (doMx) {
                        acc[k].x -= max3f(amx.x, bmx.x, cmx.x);
                        acc[k].y -= max3f(amx.y, bmx.y, cmx.y);
                        acc[k].z -= max3f(amx.z, bmx.z, cmx.z);
                        acc[k].w -= max3f(amx.w, bmx.w, cmx.w);
                    }
                    if (doE) {
                        acc[k].x += bv.x; acc[k].y += bv.y;
                        acc[k].z += bv.z; acc[k].w += bv.w;
                    }
                }
                // erode -> x_{p+1}
                if (doE && y >= elo && y < ehi) {
                    float4 e;
                    e.x = min3f(amn.x, bmn.x, cmn.x);
                    e.y = min3f(amn.y, bmn.y, cmn.y);
                    e.z = min3f(amn.z, bmn.z, cmn.z);
                    e.w = min3f(amn.w, bmn.w, cmn.w);
                    *(float4*)(nxt + y * RWP + xb) = e;
                }
                av = bv; amn = bmn; amx = bmx;
                bv = cv; bmn = cmn; bmx = cmx;
            }
        }
        __syncthreads();

        // image-border ring fix-up on freshly eroded buffer (edge blocks only):
        // halo cells adjacent to the interior must hold exact boundary
        // replicas of e for the dilate to implement clipped max.
        if (doE && anyE) {
            if (tid < TW + 2) {                              // top/bottom rows
                int o = HALO - 1 + tid;                      // col 11..140
                int sx = o;
                if (leftE  && sx < HALO)            sx = HALO;
                if (rightE && sx > HALO + TW - 1)   sx = HALO + TW - 1;
                if (topE) nxt[(HALO - 1) * RWP + o]   = nxt[HALO * RWP + sx];
                if (botE) nxt[(HALO + TH) * RWP + o]  = nxt[(HALO + TH - 1) * RWP + sx];
            } else if (tid >= 192 && tid < 192 + TH + 2) {   // left/right cols
                int o = HALO - 1 + (tid - 192);              // row 11..76
                int sy = o;
                if (topE && sy < HALO)              sy = HALO;
                if (botE && sy > HALO + TH - 1)     sy = HALO + TH - 1;
                if (leftE)  nxt[o * RWP + (HALO - 1)]  = nxt[sy * RWP + HALO];
                if (rightE) nxt[o * RWP + (HALO + TW)] = nxt[sy * RWP + (HALO + TW - 1)];
            }
            __syncthreads();
        }

        if (doE) { float* t = cur; cur = nxt; nxt = t; }
    }

    // ---- outputs ----
    if (dcol) {
        float* so = skel + (size_t)bz * IMG * IMG;
        float* xo = xout + (size_t)bz * IMG * IMG;
#pragma unroll
        for (int k = 0; k < RPS; k++) {
            const int y = y0 + k;
            if (y >= HALO && y < HALO + TH) {
                const size_t off = (size_t)(by * TH + (y - HALO)) * IMG
                                 + (size_t)(bx * TW + (xb - HALO));
                if (writex)
                    *(float4*)(xo + off) = *(const float4*)(cur + y * RWP + xb);
                if (accum) {
                    float4 sv = *(const float4*)(so + off);
                    sv.x += acc[k].x; sv.y += acc[k].y;
                    sv.z += acc[k].z; sv.w += acc[k].w;
                    *(float4*)(so + off) = sv;
                } else {
                    *(float4*)(so + off) = acc[k];
                }
            }
        }
    }
}

extern "C" void kernel_launch(void* const* d_in, const int* in_sizes, int n_in,
                              void* d_out, int out_size)
{
    (void)in_sizes; (void)n_in; (void)out_size;
    const float* x = (const float*)d_in[0];
    float* skel = (float*)d_out;

    float* scratch = nullptr;
    cudaGetSymbolAddress((void**)&scratch, g_scratch);

    cudaFuncSetAttribute(skel_merged_kernel,
                         cudaFuncAttributeMaxDynamicSharedMemorySize, SMEMB);

    dim3 grid(IMG / TW, IMG / TH, NIMG);   // 8 x 16 x 16 = 2048 CTAs
    // iterations 0..10 (11 terms): init skel, write x_11 to scratch
    skel_merged_kernel<<<grid, NT, SMEMB>>>(x, scratch, skel, 11, 0, 1);
    // iterations 11..20 (10 terms): accumulate skel
    skel_merged_kernel<<<grid, NT, SMEMB>>>(scratch, scratch, skel, 10, 1, 0);
}

// round 9
// speedup vs baseline: 1.5865x; 1.5865x over previous
#include <cuda_runtime.h>

//
// Morphological skeleton — merged erode+dilate, one smem pass per iteration.
// R8: plane-of-4 (SoA by x%4) shared layout => all neighbor accesses are
// conflict-free scalar LDS/STS; image-border handling folded into in-thread
// register clipping of the dilate operands (no fix-up pass, no 2nd barrier).
//
//   skel = sum_{j=0..K-1} x_j  -  sum_{j=1..K} dilate3(x_j),  x_{j+1} = erode3(x_j)
//
// Halo invariant: out-of-image halo cells are only ever >= the true clipped
// iterate ("min-safe"), which is harmless for erosion; dilation operands are
// clipped in registers at image boundaries, so the halo never needs fixing.
//

#define IMG    1024
#define NIMG   16
#define TILE   128
#define HALO   12
#define RW     152                /* region rows / valid cols          */
#define NCOL   38                 /* float4-column count (4*38 = 152)  */
#define NCOLP  40                 /* padded col stride in each plane   */
#define PL     (RW*NCOLP)         /* 6080 floats per plane             */
#define BUF    (4*PL)             /* 24320 floats per buffer           */
#define NSTR   16
#define NT     (NCOL*NSTR)        /* 608 threads = 19 warps            */
#define RPS    10                 /* rows per strip                    */
#define SMEMB  (2*BUF*4)          /* 194560 bytes                      */

__device__ float g_scratch[(size_t)NIMG * IMG * IMG];

__device__ __forceinline__ float mn3(float a, float b, float c) { return fminf(fminf(a, b), c); }
__device__ __forceinline__ float mx3(float a, float b, float c) { return fmaxf(fmaxf(a, b), c); }

struct Row {
    float p0, p1, p2, p3;          // raw x at cols 4c..4c+3
    float mn0, mn1, mn2, mn3;      // horizontal 3-min
    float mx0, mx1, mx2, mx3;      // horizontal 3-max (border-clipped)
};

// One row: 6 conflict-free scalar LDS -> raw vals + h-min + h-max.
__device__ __forceinline__ void loadrow(const float* __restrict__ b, int y, int c,
                                        bool doMn, bool doMx, bool lClip, bool rClip,
                                        Row& o)
{
    const int off = y * NCOLP + c;
    const float p0 = b[off];
    const float p1 = b[PL + off];
    const float p2 = b[2*PL + off];
    const float p3 = b[3*PL + off];
    const float l  = (c > 0)        ? b[3*PL + off - 1] : p0;  // x[4c-1]
    const float r  = (c < NCOL - 1) ? b[off + 1]        : p3;  // x[4c+4]
    o.p0 = p0; o.p1 = p1; o.p2 = p2; o.p3 = p3;
    if (doMn) {
        o.mn0 = mn3(l,  p0, p1);
        o.mn1 = mn3(p0, p1, p2);
        o.mn2 = mn3(p1, p2, p3);
        o.mn3 = mn3(p2, p3, r);
    }
    if (doMx) {
        const float lx = lClip ? p0 : l;   // image-left: clipped max
        const float rx = rClip ? p3 : r;   // image-right
        o.mx0 = mx3(lx, p0, p1);
        o.mx1 = mx3(p0, p1, p2);
        o.mx2 = mx3(p1, p2, p3);
        o.mx3 = mx3(p2, p3, rx);
    }
}

__global__ void __launch_bounds__(NT, 1)
skel_kernel(const float* __restrict__ xin,
            float* __restrict__ xout,
            float* __restrict__ skel,
            int K, int accum, int writex)
{
    extern __shared__ float smem[];
    float* cur = smem;          // planes of x_p
    float* nxt = smem + BUF;    // receives x_{p+1}

    const int tid = threadIdx.x;
    const int bx = blockIdx.x, by = blockIdx.y, bz = blockIdx.z;
    const int gx0 = bx * TILE - HALO;
    const int gy0 = by * TILE - HALO;
    const float* img = xin + (size_t)bz * IMG * IMG;

    // ---- initial load into plane layout ----
    if (gx0 >= 0 && gx0 + RW <= IMG) {
        for (int u = tid; u < RW * NCOL; u += NT) {
            const int y = u / NCOL, c = u - y * NCOL;
            const int gy = min(max(gy0 + y, 0), IMG - 1);
            const float4 v = *(const float4*)(img + (size_t)gy * IMG + gx0 + 4 * c);
            const int off = y * NCOLP + c;
            cur[off] = v.x; cur[PL + off] = v.y;
            cur[2*PL + off] = v.z; cur[3*PL + off] = v.w;
        }
    } else {
        for (int u = tid; u < RW * NCOL; u += NT) {
            const int y = u / NCOL, c = u - y * NCOL;
            const int gy = min(max(gy0 + y, 0), IMG - 1);
            const float* rowp = img + (size_t)gy * IMG;
            const int off = y * NCOLP + c;
#pragma unroll
            for (int m = 0; m < 4; m++) {
                const int gx = min(max(gx0 + 4 * c + m, 0), IMG - 1);
                cur[m * PL + off] = rowp[gx];
            }
        }
    }
    __syncthreads();

    const bool topE   = (by == 0);
    const bool botE   = (by == (int)gridDim.y - 1);
    const bool leftE  = (bx == 0);
    const bool rightE = (bx == (int)gridDim.x - 1);

    const int c  = tid % NCOL;                 // plane column 0..37
    const int s  = tid / NCOL;                 // strip 0..15
    const int y0 = s * RPS;
    const bool dcol  = (c >= 3) && (c <= 34);  // image-interior column block
    const bool lClip = leftE  && (c == 3);     // block containing image col 0
    const bool rClip = rightE && (c == 34);    // block containing image col 1023

    float4 acc[RPS];
#pragma unroll
    for (int k = 0; k < RPS; k++) acc[k] = make_float4(0.f, 0.f, 0.f, 0.f);

    for (int p = 0; p <= K; ++p) {
        const bool doE  = (p < K);
        const bool doD  = (p > 0);
        const bool doMx = doD && dcol;
        const int  m    = K - p;                       // erode validity margin
        const int  elo  = doE ? (HALO - m) : HALO;     // >= 1
        const int  ehi  = doE ? (HALO + TILE + m) : (HALO + TILE);  // <= 151

        if (doE || doMx) {
            Row A, B, C;
            loadrow(cur, max(y0 - 1, 0), c, doE, doMx, lClip, rClip, A);
            loadrow(cur, y0,             c, doE, doMx, lClip, rClip, B);
#pragma unroll
            for (int k = 0; k < RPS; k++) {
                const int y = y0 + k;
                loadrow(cur, min(y + 1, RW - 1), c, doE, doMx, lClip, rClip, C);

                if (doMx && y >= HALO && y < HALO + TILE) {
                    // vertical clipping at image top/bottom rows (in registers)
                    const bool tC = topE && (y == HALO);
                    const bool bC = botE && (y == HALO + TILE - 1);
                    const float a0 = tC ? B.mx0 : A.mx0, a1 = tC ? B.mx1 : A.mx1;
                    const float a2 = tC ? B.mx2 : A.mx2, a3 = tC ? B.mx3 : A.mx3;
                    const float c0 = bC ? B.mx0 : C.mx0, c1 = bC ? B.mx1 : C.mx1;
                    const float c2 = bC ? B.mx2 : C.mx2, c3 = bC ? B.mx3 : C.mx3;
                    const float d0 = mx3(a0, B.mx0, c0);
                    const float d1 = mx3(a1, B.mx1, c1);
                    const float d2 = mx3(a2, B.mx2, c2);
                    const float d3 = mx3(a3, B.mx3, c3);
                    if (doE) {   // +x_p - d(x_p)
                        acc[k].x += B.p0 - d0; acc[k].y += B.p1 - d1;
                        acc[k].z += B.p2 - d2; acc[k].w += B.p3 - d3;
                    } else {     // last pass: -d(x_K) only
                        acc[k].x -= d0; acc[k].y -= d1;
                        acc[k].z -= d2; acc[k].w -= d3;
                    }
                } else if (doE && dcol && y >= HALO && y < HALO + TILE) {
                    // p == 0: +x_0 term only
                    acc[k].x += B.p0; acc[k].y += B.p1;
                    acc[k].z += B.p2; acc[k].w += B.p3;
                }

                if (doE && y >= elo && y < ehi) {
                    const int off = y * NCOLP + c;
                    nxt[off]        = mn3(A.mn0, B.mn0, C.mn0);
                    nxt[PL + off]   = mn3(A.mn1, B.mn1, C.mn1);
                    nxt[2*PL + off] = mn3(A.mn2, B.mn2, C.mn2);
                    nxt[3*PL + off] = mn3(A.mn3, B.mn3, C.mn3);
                }
                A = B; B = C;
            }
        }
        __syncthreads();
        if (doE) { float* t = cur; cur = nxt; nxt = t; }
    }

    // ---- outputs ----
    if (dcol) {
        float* so = skel + (size_t)bz * IMG * IMG;
        float* xo = xout + (size_t)bz * IMG * IMG;
        const int gxo = bx * TILE + 4 * (c - 3);
#pragma unroll
        for (int k = 0; k < RPS; k++) {
            const int y = y0 + k;
            if (y >= HALO && y < HALO + TILE) {
                const size_t off = (size_t)(by * TILE + (y - HALO)) * IMG + gxo;
                if (writex) {
                    const int o = y * NCOLP + c;
                    float4 v = make_float4(cur[o], cur[PL + o],
                                           cur[2*PL + o], cur[3*PL + o]);
                    *(float4*)(xo + off) = v;
                }
                if (accum) {
                    float4 sv = *(const float4*)(so + off);
                    sv.x += acc[k].x; sv.y += acc[k].y;
                    sv.z += acc[k].z; sv.w += acc[k].w;
                    *(float4*)(so + off) = sv;
                } else {
                    *(float4*)(so + off) = acc[k];
                }
            }
        }
    }
}

extern "C" void kernel_launch(void* const* d_in, const int* in_sizes, int n_in,
                              void* d_out, int out_size)
{
    (void)in_sizes; (void)n_in; (void)out_size;
    const float* x = (const float*)d_in[0];
    float* skel = (float*)d_out;

    float* scratch = nullptr;
    cudaGetSymbolAddress((void**)&scratch, g_scratch);

    cudaFuncSetAttribute(skel_kernel,
                         cudaFuncAttributeMaxDynamicSharedMemorySize, SMEMB);

    dim3 grid(IMG / TILE, IMG / TILE, NIMG);   // 8 x 8 x 16
    // iterations 0..10 (11 terms): init skel, write x_11 to scratch
    skel_kernel<<<grid, NT, SMEMB>>>(x, scratch, skel, 11, 0, 1);
    // iterations 11..20 (10 terms): accumulate skel
    skel_kernel<<<grid, NT, SMEMB>>>(scratch, scratch, skel, 10, 1, 0);
}

// round 10
// speedup vs baseline: 1.6039x; 1.0110x over previous
#include <cuda_runtime.h>

//
// Morphological skeleton — merged erode+dilate, one smem pass per iteration.
// R9: pair-plane smem layout (float2 SoA: planes for {x0,x1} and {x2,x3} of
// each 4-pixel block) => center loads are LDS.64, neighbor loads are 2-way
// (not 4-way) conflicted scalars, erode stores are STS.64 — 25% less crossbar
// than the AoS float4 layout with only one extra load instruction.
// Image-border handling is in-register clipping of dilate operands (no fix-up
// pass, one barrier per iteration).
//
//   skel = sum_{j=0..K-1} x_j  -  sum_{j=1..K} dilate3(x_j),  x_{j+1} = erode3(x_j)
//
// Halo invariant: out-of-image halo cells are only ever >= the true clipped
// iterate ("min-safe") — harmless for erosion; dilation operands are clipped
// in registers at image boundaries, so the halo never needs fixing.
//

#define IMG    1024
#define NIMG   16
#define TILE   128
#define HALO   12
#define RW     152                /* region rows / valid cols           */
#define NCOL   38                 /* 4-pixel blocks per row (4*38=152)  */
#define PRS    80                 /* plane row stride in floats (40*2)  */
#define PLSZ   (RW*PRS)           /* 12160 floats per plane             */
#define BUFSZ  (2*PLSZ)           /* 24320 floats per buffer            */
#define NSTR   16
#define NT     (NCOL*NSTR)        /* 608 threads = 19 warps             */
#define RPS    10                 /* rows per strip                     */
#define SMEMB  (2*BUFSZ*4)        /* 194560 bytes                       */

__device__ float g_scratch[(size_t)NIMG * IMG * IMG];

__device__ __forceinline__ float mn3(float a, float b, float c) { return fminf(fminf(a, b), c); }
__device__ __forceinline__ float mx3(float a, float b, float c) { return fmaxf(fmaxf(a, b), c); }

struct Row {
    float p0, p1, p2, p3;          // raw x at cols 4c..4c+3
    float mn0, mn1, mn2, mn3;      // horizontal 3-min
    float mx0, mx1, mx2, mx3;      // horizontal 3-max (image-border-clipped)
};

// One row: 2x LDS.64 (center) + 2 lightly-conflicted scalar LDS (neighbors).
__device__ __forceinline__ void loadrow(const float* __restrict__ b, int y, int c,
                                        bool doMn, bool doMx, bool lClip, bool rClip,
                                        Row& o)
{
    const int oa = y * PRS + 2 * c;           // plane A slot
    const int ob = PLSZ + oa;                 // plane B slot
    const float2 ab = *(const float2*)(b + oa);
    const float2 cd = *(const float2*)(b + ob);
    const float p0 = ab.x, p1 = ab.y, p2 = cd.x, p3 = cd.y;
    const float l  = (c > 0)        ? b[ob - 1] : p0;   // x[4c-1] = planeB[c-1].y
    const float r  = (c < NCOL - 1) ? b[oa + 2] : p3;   // x[4c+4] = planeA[c+1].x
    o.p0 = p0; o.p1 = p1; o.p2 = p2; o.p3 = p3;
    if (doMn) {
        o.mn0 = mn3(l,  p0, p1);
        o.mn1 = mn3(p0, p1, p2);
        o.mn2 = mn3(p1, p2, p3);
        o.mn3 = mn3(p2, p3, r);
    }
    if (doMx) {
        const float lx = lClip ? p0 : l;   // clipped max at image-left col
        const float rx = rClip ? p3 : r;   // image-right
        o.mx0 = mx3(lx, p0, p1);
        o.mx1 = mx3(p0, p1, p2);
        o.mx2 = mx3(p1, p2, p3);
        o.mx3 = mx3(p2, p3, rx);
    }
}

__global__ void __launch_bounds__(NT, 1)
skel_kernel(const float* __restrict__ xin,
            float* __restrict__ xout,
            float* __restrict__ skel,
            int K, int accum, int writex)
{
    extern __shared__ float smem[];
    float* cur = smem;            // x_p   (plane A | plane B)
    float* nxt = smem + BUFSZ;    // receives x_{p+1}

    const int tid = threadIdx.x;
    const int bx = blockIdx.x, by = blockIdx.y, bz = blockIdx.z;
    const int gx0 = bx * TILE - HALO;
    const int gy0 = by * TILE - HALO;
    const float* img = xin + (size_t)bz * IMG * IMG;

    // ---- initial load into pair-plane layout ----
    if (gx0 >= 0 && gx0 + RW <= IMG) {
        for (int u = tid; u < RW * NCOL; u += NT) {
            const int y = u / NCOL, c = u - y * NCOL;
            const int gy = min(max(gy0 + y, 0), IMG - 1);
            const float4 v = *(const float4*)(img + (size_t)gy * IMG + gx0 + 4 * c);
            const int oa = y * PRS + 2 * c;
            *(float2*)(cur + oa)        = make_float2(v.x, v.y);
            *(float2*)(cur + PLSZ + oa) = make_float2(v.z, v.w);
        }
    } else {
        for (int u = tid; u < RW * NCOL; u += NT) {
            const int y = u / NCOL, c = u - y * NCOL;
            const int gy = min(max(gy0 + y, 0), IMG - 1);
            const float* rowp = img + (size_t)gy * IMG;
            const int oa = y * PRS + 2 * c;
            const int g0 = min(max(gx0 + 4 * c + 0, 0), IMG - 1);
            const int g1 = min(max(gx0 + 4 * c + 1, 0), IMG - 1);
            const int g2 = min(max(gx0 + 4 * c + 2, 0), IMG - 1);
            const int g3 = min(max(gx0 + 4 * c + 3, 0), IMG - 1);
            *(float2*)(cur + oa)        = make_float2(rowp[g0], rowp[g1]);
            *(float2*)(cur + PLSZ + oa) = make_float2(rowp[g2], rowp[g3]);
        }
    }
    __syncthreads();

    const bool topE   = (by == 0);
    const bool botE   = (by == (int)gridDim.y - 1);
    const bool leftE  = (bx == 0);
    const bool rightE = (bx == (int)gridDim.x - 1);

    const int c  = tid % NCOL;                 // block column 0..37
    const int s  = tid / NCOL;                 // strip 0..15
    const int y0 = s * RPS;
    const bool dcol  = (c >= 3) && (c <= 34);  // image-interior column block
    const bool lClip = leftE  && (c == 3);     // block containing image col 0
    const bool rClip = rightE && (c == 34);    // block containing image col 1023

    float4 acc[RPS];
#pragma unroll
    for (int k = 0; k < RPS; k++) acc[k] = make_float4(0.f, 0.f, 0.f, 0.f);

    for (int p = 0; p <= K; ++p) {
        const bool doE  = (p < K);
        const bool doD  = (p > 0);
        const bool doMx = doD && dcol;
        const int  m    = K - p;                       // erode validity margin
        const int  elo  = doE ? (HALO - m) : HALO;     // >= 1
        const int  ehi  = doE ? (HALO + TILE + m) : (HALO + TILE);  // <= 151

        if (doE || doMx) {
            Row A, B, C;
            loadrow(cur, max(y0 - 1, 0), c, doE, doMx, lClip, rClip, A);
            loadrow(cur, y0,             c, doE, doMx, lClip, rClip, B);
#pragma unroll
            for (int k = 0; k < RPS; k++) {
                const int y = y0 + k;
                loadrow(cur, min(y + 1, RW - 1), c, doE, doMx, lClip, rClip, C);

                if (doMx && y >= HALO && y < HALO + TILE) {
                    // vertical clipping at image top/bottom rows (registers)
                    const bool tC = topE && (y == HALO);
                    const bool bC = botE && (y == HALO + TILE - 1);
                    const float a0 = tC ? B.mx0 : A.mx0, a1 = tC ? B.mx1 : A.mx1;
                    const float a2 = tC ? B.mx2 : A.mx2, a3 = tC ? B.mx3 : A.mx3;
                    const float c0 = bC ? B.mx0 : C.mx0, c1 = bC ? B.mx1 : C.mx1;
                    const float c2 = bC ? B.mx2 : C.mx2, c3 = bC ? B.mx3 : C.mx3;
                    const float d0 = mx3(a0, B.mx0, c0);
                    const float d1 = mx3(a1, B.mx1, c1);
                    const float d2 = mx3(a2, B.mx2, c2);
                    const float d3 = mx3(a3, B.mx3, c3);
                    if (doE) {   // +x_p - d(x_p)
                        acc[k].x += B.p0 - d0; acc[k].y += B.p1 - d1;
                        acc[k].z += B.p2 - d2; acc[k].w += B.p3 - d3;
                    } else {     // last pass: -d(x_K) only
                        acc[k].x -= d0; acc[k].y -= d1;
                        acc[k].z -= d2; acc[k].w -= d3;
                    }
                } else if (doE && dcol && y >= HALO && y < HALO + TILE) {
                    // p == 0: +x_0 term only
                    acc[k].x += B.p0; acc[k].y += B.p1;
                    acc[k].z += B.p2; acc[k].w += B.p3;
                }

                if (doE && y >= elo && y < ehi) {
                    const int oa = y * PRS + 2 * c;
                    *(float2*)(nxt + oa) =
                        make_float2(mn3(A.mn0, B.mn0, C.mn0),
                                    mn3(A.mn1, B.mn1, C.mn1));
                    *(float2*)(nxt + PLSZ + oa) =
                        make_float2(mn3(A.mn2, B.mn2, C.mn2),
                                    mn3(A.mn3, B.mn3, C.mn3));
                }
                A = B; B = C;
            }
        }
        __syncthreads();
        if (doE) { float* t = cur; cur = nxt; nxt = t; }
    }

    // ---- outputs ----
    if (dcol) {
        float* so = skel + (size_t)bz * IMG * IMG;
        float* xo = xout + (size_t)bz * IMG * IMG;
        const int gxo = bx * TILE + 4 * (c - 3);
#pragma unroll
        for (int k = 0; k < RPS; k++) {
            const int y = y0 + k;
            if (y >= HALO && y < HALO + TILE) {
                const size_t off = (size_t)(by * TILE + (y - HALO)) * IMG + gxo;
                if (writex) {
                    const int oa = y * PRS + 2 * c;
                    const float2 ab = *(const float2*)(cur + oa);
                    const float2 cd = *(const float2*)(cur + PLSZ + oa);
                    *(float4*)(xo + off) = make_float4(ab.x, ab.y, cd.x, cd.y);
                }
                if (accum) {
                    float4 sv = *(const float4*)(so + off);
                    sv.x += acc[k].x; sv.y += acc[k].y;
                    sv.z += acc[k].z; sv.w += acc[k].w;
                    *(float4*)(so + off) = sv;
                } else {
                    *(float4*)(so + off) = acc[k];
                }
            }
        }
    }
}

extern "C" void kernel_launch(void* const* d_in, const int* in_sizes, int n_in,
                              void* d_out, int out_size)
{
    (void)in_sizes; (void)n_in; (void)out_size;
    const float* x = (const float*)d_in[0];
    float* skel = (float*)d_out;

    float* scratch = nullptr;
    cudaGetSymbolAddress((void**)&scratch, g_scratch);

    cudaFuncSetAttribute(skel_kernel,
                         cudaFuncAttributeMaxDynamicSharedMemorySize, SMEMB);

    dim3 grid(IMG / TILE, IMG / TILE, NIMG);   // 8 x 8 x 16
    // iterations 0..10 (11 terms): init skel, write x_11 to scratch
    skel_kernel<<<grid, NT, SMEMB>>>(x, scratch, skel, 11, 0, 1);
    // iterations 11..20 (10 terms): accumulate skel
    skel_kernel<<<grid, NT, SMEMB>>>(scratch, scratch, skel, 10, 1, 0);
}

// round 11
// speedup vs baseline: 2.0728x; 1.2923x over previous
#include <cuda_runtime.h>

//
// Morphological skeleton — merged erode+dilate, one smem pass per iteration.
// R10 = R6 (best: 541us) with 19 strips x 8 rows => 722 threads (22.6 warps)
// instead of 16 x 10 => 608. Profile showed no saturated pipe at 19 warps
// (issue 42%, L1 58%, alu 33%) -> latency-bound; add warps to hide LDS+barrier.
//
//   skel = sum_{j=0..K-1} x_j  -  sum_{j=1..K} dilate3(x_j),  x_{j+1} = erode3(x_j)
//

#define IMG    1024
#define NIMG   16
#define TILE   128
#define HALO   12
#define RW     152                 /* region valid width/height   */
#define RWP    164                 /* padded row stride: 164%32=4 avoids cross-strip bank aliasing */
#define NCOL   38                  /* float4 columns: exactly covers 152 */
#define NSTR   19
#define NT     (NCOL*NSTR)         /* 722 threads ~ 22.6 warps    */
#define RPS    8                   /* rows per strip: 19*8 = 152 exactly */
#define SMEMB  (2 * RW * RWP * 4)  /* 199424 bytes                */

__device__ float g_scratch[(size_t)NIMG * IMG * IMG];

__device__ __forceinline__ float min3f(float a, float b, float c) { return fminf(fminf(a, b), c); }
__device__ __forceinline__ float max3f(float a, float b, float c) { return fmaxf(fmaxf(a, b), c); }

// One row-block: 1x LDS.128 + 2x independent scalar LDS (no shuffles — the
// scalar loads overlap with the vector load; shfl serializes, measured 2x).
__device__ __forceinline__ void rowmm(const float* __restrict__ row, int xb,
                                      float4& v, float4& mn, float4& mx,
                                      bool doMn, bool doMx)
{
    v = *(const float4*)(row + xb);
    float l = (xb > 0)       ? row[xb - 1] : v.x;   // region-edge replicate (min-safe;
    float r = (xb + 4 < RW)  ? row[xb + 4] : v.w;   //  never feeds interior dilate)
    if (doMn) {
        mn.x = min3f(l,   v.x, v.y);
        mn.y = min3f(v.x, v.y, v.z);
        mn.z = min3f(v.y, v.z, v.w);
        mn.w = min3f(v.z, v.w, r);
    }
    if (doMx) {
        mx.x = max3f(l,   v.x, v.y);
        mx.y = max3f(v.x, v.y, v.z);
        mx.z = max3f(v.y, v.z, v.w);
        mx.w = max3f(v.z, v.w, r);
    }
}

__global__ void __launch_bounds__(NT, 1)
skel_merged_kernel(const float* __restrict__ xin,
                   float* __restrict__ xout,
                   float* __restrict__ skel,
                   int K, int accum, int writex)
{
    extern __shared__ float smem[];
    float* cur = smem;             // x_p
    float* nxt = smem + RW * RWP;  // receives x_{p+1}

    const int tid = threadIdx.x;
    const int bx = blockIdx.x, by = blockIdx.y, bz = blockIdx.z;
    const int gx0 = bx * TILE - HALO;
    const int gy0 = by * TILE - HALO;
    const float* img = xin + (size_t)bz * IMG * IMG;

    // ---- load region with replicate clamp ----
    for (int i = tid; i < RW * RW; i += NT) {
        int y = i / RW;
        int x = i - y * RW;
        int gy = min(max(gy0 + y, 0), IMG - 1);
        int gx = min(max(gx0 + x, 0), IMG - 1);
        cur[y * RWP + x] = img[(size_t)gy * IMG + gx];
    }
    __syncthreads();

    const bool topE   = (by == 0);
    const bool botE   = (by == (int)gridDim.y - 1);
    const bool leftE  = (bx == 0);
    const bool rightE = (bx == (int)gridDim.x - 1);
    const bool anyE   = topE || botE || leftE || rightE;

    const int c  = tid % NCOL;                   // float4 column 0..37
    const int s  = tid / NCOL;                   // strip 0..18
    const int xb = c * 4;                        // 0..148
    const bool dcol = (xb >= HALO) && (xb + 4 <= HALO + TILE);  // interior col block
    const int y0 = s * RPS;

    float4 acc[RPS];
#pragma unroll
    for (int k = 0; k < RPS; k++) acc[k] = make_float4(0.f, 0.f, 0.f, 0.f);

    for (int p = 0; p <= K; ++p) {
        const bool doE = (p < K);
        const bool doD = (p > 0);
        const bool doMx = doD && dcol;           // hmax consumed only here
        const int  m   = K - p;                  // erode validity margin
        const int  elo = doE ? (HALO - m) : HALO;
        const int  ehi = doE ? (HALO + TILE + m) : (HALO + TILE);

        if (doE || dcol) {
            // prime 3-row ring (vertical replicate clamp; min-safe, clamped
            // rows never reach interior dilate consumers)
            float4 av, amn, amx, bv, bmn, bmx;
            rowmm(cur + max(y0 - 1, 0) * RWP, xb, av, amn, amx, doE, doMx);
            rowmm(cur + y0 * RWP,             xb, bv, bmn, bmx, doE, doMx);

#pragma unroll
            for (int k = 0; k < RPS; k++) {
                const int y = y0 + k;
                float4 cv, cmn, cmx;
                rowmm(cur + min(y + 1, RW - 1) * RWP, xb, cv, cmn, cmx, doE, doMx);

                // skel terms at interior rows: += x_p (p<K), -= dilate(x_p) (p>0)
                if (dcol && y >= HALO && y < HALO + TILE) {
                    if (doMx) {
                        acc[k].x -= max3f(amx.x, bmx.x, cmx.x);
                        acc[k].y -= max3f(amx.y, bmx.y, cmx.y);
                        acc[k].z -= max3f(amx.z, bmx.z, cmx.z);
                        acc[k].w -= max3f(amx.w, bmx.w, cmx.w);
                    }
                    if (doE) {
                        acc[k].x += bv.x; acc[k].y += bv.y;
                        acc[k].z += bv.z; acc[k].w += bv.w;
                    }
                }
                // erode -> x_{p+1}
                if (doE && y >= elo && y < ehi) {
                    float4 e;
                    e.x = min3f(amn.x, bmn.x, cmn.x);
                    e.y = min3f(amn.y, bmn.y, cmn.y);
                    e.z = min3f(amn.z, bmn.z, cmn.z);
                    e.w = min3f(amn.w, bmn.w, cmn.w);
                    *(float4*)(nxt + y * RWP + xb) = e;
                }
                av = bv; amn = bmn; amx = bmx;
                bv = cv; bmn = cmn; bmx = cmx;
            }
        }
        __syncthreads();

        // image-border ring fix-up on freshly eroded buffer (edge blocks only)
        if (doE && anyE) {
            if (tid < TILE + 2) {
                int o = HALO - 1 + tid;                    // 11..140
                int sx = o;
                if (leftE  && sx < HALO)             sx = HALO;
                if (rightE && sx > HALO + TILE - 1)  sx = HALO + TILE - 1;
                int sy = o;
                if (topE && sy < HALO)               sy = HALO;
                if (botE && sy > HALO + TILE - 1)    sy = HALO + TILE - 1;
                if (topE)   nxt[(HALO - 1) * RWP + o]      = nxt[HALO * RWP + sx];
                if (botE)   nxt[(HALO + TILE) * RWP + o]   = nxt[(HALO + TILE - 1) * RWP + sx];
                if (leftE)  nxt[o * RWP + (HALO - 1)]      = nxt[sy * RWP + HALO];
                if (rightE) nxt[o * RWP + (HALO + TILE)]   = nxt[sy * RWP + (HALO + TILE - 1)];
            }
            __syncthreads();
        }

        if (doE) { float* t = cur; cur = nxt; nxt = t; }
    }

    // ---- outputs ----
    if (dcol) {
        float* so = skel + (size_t)bz * IMG * IMG;
        float* xo = xout + (size_t)bz * IMG * IMG;
#pragma unroll
        for (int k = 0; k < RPS; k++) {
            const int y = y0 + k;
            if (y >= HALO && y < HALO + TILE) {
                const size_t off = (size_t)(by * TILE + (y - HALO)) * IMG
                                 + (size_t)(bx * TILE + (xb - HALO));
                if (writex)
                    *(float4*)(xo + off) = *(const float4*)(cur + y * RWP + xb);
                if (accum) {
                    float4 sv = *(const float4*)(so + off);
                    sv.x += acc[k].x; sv.y += acc[k].y;
                    sv.z += acc[k].z; sv.w += acc[k].w;
                    *(float4*)(so + off) = sv;
                } else {
                    *(float4*)(so + off) = acc[k];
                }
            }
        }
    }
}

extern "C" void kernel_launch(void* const* d_in, const int* in_sizes, int n_in,
                              void* d_out, int out_size)
{
    (void)in_sizes; (void)n_in; (void)out_size;
    const float* x = (const float*)d_in[0];
    float* skel = (float*)d_out;

    float* scratch = nullptr;
    cudaGetSymbolAddress((void**)&scratch, g_scratch);

    cudaFuncSetAttribute(skel_merged_kernel,
                         cudaFuncAttributeMaxDynamicSharedMemorySize, SMEMB);

    dim3 grid(IMG / TILE, IMG / TILE, NIMG);   // 8 x 8 x 16
    // iterations 0..10 (11 terms): init skel, write x_11 to scratch
    skel_merged_kernel<<<grid, NT, SMEMB>>>(x, scratch, skel, 11, 0, 1);
    // iterations 11..20 (10 terms): accumulate skel
    skel_merged_kernel<<<grid, NT, SMEMB>>>(scratch, scratch, skel, 10, 1, 0);
}